// round 15
// baseline (speedup 1.0000x reference)
#include <cuda_runtime.h>
#include <cuda_bf16.h>
#include <math.h>

typedef unsigned long long ull;
typedef unsigned int u32;
typedef unsigned short u16;

#define NCTA 132                 // 128 compute + 4 head
// dynamic smem float offsets (compute CTAs)
#define OFF_C_F  40960           // C tile (64 x 82)
#define OFF_BS_F 46208           // 80 bias floats
#define SMEM_BYTES 185344

// ---------------- persistent device state (no allocations) -----------------
// W fragments interleaved: [((cs*10+ti)*32+kg)*32+lane][4] = {bH0,bH1,bL0,bL1}
__device__ u32 g_Wcomb[1310720];
// h and z in A-fragment layout: [buf][split][rblk][wr][kg][lane][4 u32]
__device__ u32 g_hfrag[2 * 2 * 4 * 4 * 32 * 32 * 4];
__device__ u32 g_zfrag[2 * 2 * 4 * 4 * 32 * 32 * 4];
// W2 B-fragments: [split][kg][nt][lane][2 u32]  (n padded 9->16)
__device__ u32 g_W2frag[8192];
__device__ float g_ball[2560];                     // gate cols j'=4u+g, then b1
__device__ float g_c[256 * 512];
__device__ u32 g_flags[NCTA];

// ---------------- helpers ----------------------------------------------------
__device__ __forceinline__ float fsig(float x) {
    return __fdividef(1.f, 1.f + __expf(-x));
}
__device__ __forceinline__ float ftanh(float x) {
    return 2.f * fsig(2.f * x) - 1.f;
}
__device__ __forceinline__ void split_bf16(float v, __nv_bfloat16& hi, __nv_bfloat16& lo) {
    hi = __float2bfloat16_rn(v);
    lo = __float2bfloat16_rn(v - __bfloat162float(hi));
}

// distributed-flag grid barrier: per-CTA release store, per-thread acquire poll
__device__ __forceinline__ void gbar(int p) {
    __syncthreads();
    if (threadIdx.x == 0) {
        asm volatile("st.release.gpu.global.u32 [%0], %1;"
                     :: "l"(&g_flags[blockIdx.x]), "r"((u32)p) : "memory");
    }
    if (threadIdx.x < NCTA) {
        u32 e;
        do {
            asm volatile("ld.acquire.gpu.global.u32 %0, [%1];"
                         : "=r"(e) : "l"(&g_flags[threadIdx.x]) : "memory");
        } while (e < (u32)p);
    }
    __syncthreads();
}

__device__ __forceinline__ void mma16816(float* d, u32 a0, u32 a1, u32 a2, u32 a3,
                                         u32 b0, u32 b1) {
    asm volatile("mma.sync.aligned.m16n8k16.row.col.f32.bf16.bf16.f32 "
                 "{%0,%1,%2,%3},{%4,%5,%6,%7},{%8,%9},{%0,%1,%2,%3};"
                 : "+f"(d[0]), "+f"(d[1]), "+f"(d[2]), "+f"(d[3])
                 : "r"(a0), "r"(a1), "r"(a2), "r"(a3), "r"(b0), "r"(b1));
}

// write value(fp32) into A-fragment layout (hi and lo splits), single element
__device__ __forceinline__ void store_frag(u32* fragbase, int buf, int row, int u, float v) {
    int rblk = row >> 6, rl = row & 63;
    int wr = rl >> 4, rloc = rl & 15;
    int kg = u >> 4, kkl = u & 15;
    int lane = (rloc & 7) * 4 + ((kkl & 7) >> 1);
    int reg = ((kkl >> 3) & 1) * 2 + ((rloc >> 3) & 1);
    int half = kkl & 1;
    __nv_bfloat16 hi, lo; split_bf16(v, hi, lo);
    u32 idxH = ((((u32)(buf * 2 + 0) * 4 + rblk) * 4 + wr) * 32 + kg) * 128 + lane * 4 + reg;
    u32 idxL = ((((u32)(buf * 2 + 1) * 4 + rblk) * 4 + wr) * 32 + kg) * 128 + lane * 4 + reg;
    ((u16*)fragbase)[idxH * 2 + half] = __bfloat16_as_ushort(hi);
    ((u16*)fragbase)[idxL * 2 + half] = __bfloat16_as_ushort(lo);
}

// paired store: u0 even; writes (u0, u0+1) as one u32 per split
// buf/split stride = 4*4*32*128 = 65536 u32
__device__ __forceinline__ void store_frag_pair(u32* fragbase, int buf, int row, int u0,
                                                float v0, float v1) {
    int rblk = row >> 6, rl = row & 63;
    int wr = rl >> 4, rloc = rl & 15;
    int kg = u0 >> 4, kkl = u0 & 15;          // kkl even
    int lane = (rloc & 7) * 4 + ((kkl & 7) >> 1);
    int reg = ((kkl >> 3) & 1) * 2 + ((rloc >> 3) & 1);
    __nv_bfloat16 h0, l0, h1, l1;
    split_bf16(v0, h0, l0); split_bf16(v1, h1, l1);
    u32 hv = (u32)__bfloat16_as_ushort(h0) | ((u32)__bfloat16_as_ushort(h1) << 16);
    u32 lv = (u32)__bfloat16_as_ushort(l0) | ((u32)__bfloat16_as_ushort(l1) << 16);
    u32 base = (((u32)rblk * 4 + wr) * 32 + kg) * 128 + lane * 4 + reg;
    fragbase[(u32)(buf * 2 + 0) * 65536 + base] = hv;
    fragbase[(u32)(buf * 2 + 1) * 65536 + base] = lv;
}

// ---------------- prep kernels -----------------------------------------------
__device__ __forceinline__ float wall_val(const float* Wih, const float* Whh,
                                          const float* W1, int cs, int k) {
    if (cs < 2048) { int j = (cs & 3) * 512 + (cs >> 2);
                     return Wih[j * 512 + k] + Whh[j * 512 + k]; }
    return W1[(cs - 2048) * 512 + k];
}
__global__ void prepWfrag(const float* __restrict__ Wih, const float* __restrict__ Whh,
                          const float* __restrict__ W1) {
    int gid = blockIdx.x * 256 + threadIdx.x;       // 1,310,720 u32 entries
    int e = gid & 3;
    int lane = (gid >> 2) & 31;
    int kg = (gid >> 7) & 31;
    int rem = gid >> 12;                            // cs*10+ti
    int ti = rem % 10, cs = rem / 10;
    int col = cs * 80 + ti * 8 + (lane >> 2);
    int reg = e & 1, split = e >> 1;
    int k0 = kg * 16 + (lane & 3) * 2 + reg * 8;
    float v0 = wall_val(Wih, Whh, W1, col, k0);
    float v1 = wall_val(Wih, Whh, W1, col, k0 + 1);
    __nv_bfloat16 h0, l0, h1, l1;
    split_bf16(v0, h0, l0); split_bf16(v1, h1, l1);
    u32 val;
    if (split == 0)
        val = (u32)__bfloat16_as_ushort(h0) | ((u32)__bfloat16_as_ushort(h1) << 16);
    else
        val = (u32)__bfloat16_as_ushort(l0) | ((u32)__bfloat16_as_ushort(l1) << 16);
    g_Wcomb[gid] = val;
}
__global__ void prepW2frag(const float* __restrict__ W2) {
    int gid = blockIdx.x * 256 + threadIdx.x;       // 8192
    int reg = gid & 1, lane = (gid >> 1) & 31;
    int nt = (gid >> 6) & 1, kg = (gid >> 7) & 31, split = (gid >> 12) & 1;
    int n = nt * 8 + (lane >> 2);
    int k0 = kg * 16 + (lane & 3) * 2 + reg * 8;
    float v0 = (n < 9) ? W2[n * 512 + k0] : 0.f;
    float v1 = (n < 9) ? W2[n * 512 + k0 + 1] : 0.f;
    __nv_bfloat16 h0, l0, h1, l1;
    split_bf16(v0, h0, l0); split_bf16(v1, h1, l1);
    u32 val;
    if (split == 0)
        val = (u32)__bfloat16_as_ushort(h0) | ((u32)__bfloat16_as_ushort(h1) << 16);
    else
        val = (u32)__bfloat16_as_ushort(l0) | ((u32)__bfloat16_as_ushort(l1) << 16);
    g_W2frag[gid] = val;
}
__global__ void prepB(const float* __restrict__ bih, const float* __restrict__ bhh,
                      const float* __restrict__ b1) {
    int idx = blockIdx.x * 256 + threadIdx.x;       // 2560
    if (idx < 2048) { int u = idx >> 2, gi = idx & 3, j = gi * 512 + u;
                      g_ball[idx] = bih[j] + bhh[j]; }
    else if (idx < 2560) g_ball[idx] = b1[idx - 2048];
    if (idx < NCTA) g_flags[idx] = 0;
}

// ---------------- step 0: h(1), c(1) = cell(x, hx0, cx0), K=1024 --------------
__global__ void __launch_bounds__(256) step0_kernel(
    const float* __restrict__ x, const float* __restrict__ hx0,
    const float* __restrict__ cx0,
    const float* __restrict__ Wih, const float* __restrict__ Whh) {
    __shared__ __align__(16) float As[32 * 64];
    __shared__ __align__(16) float Wsm[32 * 64];
    const int tid = threadIdx.x, tx = tid & 15, ty = tid >> 4;
    const int ct = blockIdx.x, rb = (ct >> 5) << 6, cb = (ct & 31) << 6;
    const int r = tid & 63, s = tid >> 6;
    const int jc = cb + r, jrow = (jc & 3) * 512 + (jc >> 2);

    float acc[4][4] = {};
    for (int kc = 0; kc < 1024; kc += 32) {
        const float* Asrc = (kc < 512) ? x : hx0;
        const float* Wsrc = (kc < 512) ? Wih : Whh;
        const int kloc = (kc < 512) ? kc : kc - 512;
        __syncthreads();
#pragma unroll
        for (int h = 0; h < 2; ++h) {
            int sl = s + h * 4;
            float4 v = *(const float4*)(Asrc + (rb + r) * 512 + kloc + sl * 4);
            As[(sl * 4 + 0) * 64 + r] = v.x; As[(sl * 4 + 1) * 64 + r] = v.y;
            As[(sl * 4 + 2) * 64 + r] = v.z; As[(sl * 4 + 3) * 64 + r] = v.w;
            float4 w = *(const float4*)(Wsrc + jrow * 512 + kloc + sl * 4);
            Wsm[(sl * 4 + 0) * 64 + r] = w.x; Wsm[(sl * 4 + 1) * 64 + r] = w.y;
            Wsm[(sl * 4 + 2) * 64 + r] = w.z; Wsm[(sl * 4 + 3) * 64 + r] = w.w;
        }
        __syncthreads();
#pragma unroll 8
        for (int k = 0; k < 32; ++k) {
            float a0 = As[k * 64 + ty * 4 + 0], a1 = As[k * 64 + ty * 4 + 1];
            float a2 = As[k * 64 + ty * 4 + 2], a3 = As[k * 64 + ty * 4 + 3];
            float w0 = Wsm[k * 64 + tx * 4 + 0], w1 = Wsm[k * 64 + tx * 4 + 1];
            float w2 = Wsm[k * 64 + tx * 4 + 2], w3 = Wsm[k * 64 + tx * 4 + 3];
            acc[0][0] += a0 * w0; acc[0][1] += a0 * w1; acc[0][2] += a0 * w2; acc[0][3] += a0 * w3;
            acc[1][0] += a1 * w0; acc[1][1] += a1 * w1; acc[1][2] += a1 * w2; acc[1][3] += a1 * w3;
            acc[2][0] += a2 * w0; acc[2][1] += a2 * w1; acc[2][2] += a2 * w2; acc[2][3] += a2 * w3;
            acc[3][0] += a3 * w0; acc[3][1] += a3 * w1; acc[3][2] += a3 * w2; acc[3][3] += a3 * w3;
        }
    }
    const int u = (cb >> 2) + tx;
#pragma unroll
    for (int i = 0; i < 4; ++i) {
        int row = rb + ty * 4 + i;
        int gx = row * 512 + u;
        float vi = fsig(acc[i][0] + g_ball[cb + tx * 4 + 0]);
        float vf = fsig(acc[i][1] + g_ball[cb + tx * 4 + 1]);
        float vg = ftanh(acc[i][2] + g_ball[cb + tx * 4 + 2]);
        float vo = fsig(acc[i][3] + g_ball[cb + tx * 4 + 3]);
        float cn = vf * cx0[gx] + vi * vg;
        g_c[gx] = cn;
        store_frag(g_hfrag, 1, row, u, vo * ftanh(cn));
    }
}

// ---------------- persistent main kernel --------------------------------------
__global__ void __launch_bounds__(256, 1) main_kernel(float* __restrict__ out,
                                                      const float* __restrict__ b2) {
    extern __shared__ __align__(16) float smf[];
    const int tid = threadIdx.x, ct = blockIdx.x;

    if (ct < 128) {
        const int rblk = ct >> 5, rb = rblk << 6, cs = ct & 31, cb = cs * 80;
        const int lane = tid & 31, wid = tid >> 5;
        const int wr = wid & 3, wc = wid >> 2;          // warp: rows wr*16, cols wc*40
        const int ti0 = wc * 5;
        const int nU   = (cs < 25) ? 20 : (cs == 25 ? 12 : 0);
        const int zlc0 = (cs < 25) ? 80 : (cs == 25 ? 48 : 0);
        const int nZ = 80 - zlc0;
        const int nP = nU >> 1;                          // gate unit pairs
        const int erow = tid >> 2, eq = tid & 3, ub = cb >> 2;

        // one-time: resident W fragments (interleaved hi/lo), 160KB
        {
            const uint4* src = (const uint4*)(g_Wcomb + cs * 40960);
            uint4* dst = (uint4*)smf;
#pragma unroll
            for (int i = 0; i < 40; ++i) dst[tid + i * 256] = src[tid + i * 256];
        }
        if (tid < 80) smf[OFF_BS_F + tid] = g_ball[cb + tid];
        __syncthreads();

        const uint4* wsm = (const uint4*)smf;

        for (int t = 1; t <= 327; ++t) {
            const bool isGate = nU > 0, hasZ = nZ > 0;
            if (t <= 326 && ((t <= 325 && isGate) || hasZ)) {
                float accH[5][4], accL[5][4];
#pragma unroll
                for (int j = 0; j < 5; ++j)
#pragma unroll
                    for (int i = 0; i < 4; ++i) { accH[j][i] = 0.f; accL[j][i] = 0.f; }

                const int buf = t & 1;
                const uint4* AH = (const uint4*)g_hfrag
                    + (((u32)(buf * 2 + 0) * 4 + rblk) * 4 + wr) * 1024 + lane;
                const uint4* AL = (const uint4*)g_hfrag
                    + (((u32)(buf * 2 + 1) * 4 + rblk) * 4 + wr) * 1024 + lane;

                uint4 pH[2], pL[2];
                pH[0] = __ldcg(AH);          pL[0] = __ldcg(AL);
                pH[1] = __ldcg(AH + 32);     pL[1] = __ldcg(AL + 32);

#pragma unroll
                for (int kg = 0; kg < 32; ++kg) {
                    uint4 aH = pH[kg & 1], aL = pL[kg & 1];
                    if (kg < 30) {
                        pH[kg & 1] = __ldcg(AH + (kg + 2) * 32);
                        pL[kg & 1] = __ldcg(AL + (kg + 2) * 32);
                    }
#pragma unroll
                    for (int j = 0; j < 5; ++j) {
                        uint4 w = wsm[((ti0 + j) * 32 + kg) * 32 + lane];
                        mma16816(accH[j], aH.x, aH.y, aH.z, aH.w, w.x, w.y);
                        mma16816(accL[j], aH.x, aH.y, aH.z, aH.w, w.z, w.w);
                        mma16816(accL[j], aL.x, aL.y, aL.z, aL.w, w.x, w.y);
                    }
                }
                // D fragments -> C tile in smem (stride 82 floats)
                {
                    const int drow = wr * 16 + (lane >> 2);
                    const int dcol = wc * 40 + (lane & 3) * 2;
                    float* C0 = smf + OFF_C_F + drow * 82 + dcol;
                    float* C1 = smf + OFF_C_F + (drow + 8) * 82 + dcol;
#pragma unroll
                    for (int j = 0; j < 5; ++j) {
                        *(float2*)(C0 + j * 8) =
                            make_float2(accH[j][0] + accL[j][0], accH[j][1] + accL[j][1]);
                        *(float2*)(C1 + j * 8) =
                            make_float2(accH[j][2] + accL[j][2], accH[j][3] + accL[j][3]);
                    }
                }
                __syncthreads();

                const float* Cr = smf + OFF_C_F + erow * 82;
                const float* bb = smf + OFF_BS_F;
                const int grow = rb + erow;
                if (t <= 325 && isGate) {
                    const int nbuf = (t + 1) & 1;
#pragma unroll
                    for (int j = 0; j < 3; ++j) {
                        int pp = eq + 4 * j;
                        if (pp < nP) {
                            int lc = pp * 8;
                            int u0 = ub + 2 * pp;
                            float2 cc = *(float2*)(g_c + grow * 512 + u0);
                            float vi0 = fsig(Cr[lc + 0] + bb[lc + 0]);
                            float vf0 = fsig(Cr[lc + 1] + bb[lc + 1]);
                            float vg0 = ftanh(Cr[lc + 2] + bb[lc + 2]);
                            float vo0 = fsig(Cr[lc + 3] + bb[lc + 3]);
                            float vi1 = fsig(Cr[lc + 4] + bb[lc + 4]);
                            float vf1 = fsig(Cr[lc + 5] + bb[lc + 5]);
                            float vg1 = ftanh(Cr[lc + 6] + bb[lc + 6]);
                            float vo1 = fsig(Cr[lc + 7] + bb[lc + 7]);
                            float cn0 = vf0 * cc.x + vi0 * vg0;
                            float cn1 = vf1 * cc.y + vi1 * vg1;
                            *(float2*)(g_c + grow * 512 + u0) = make_float2(cn0, cn1);
                            store_frag_pair(g_hfrag, nbuf, grow, u0,
                                            vo0 * ftanh(cn0), vo1 * ftanh(cn1));
                        }
                    }
                }
                if (hasZ) {
#pragma unroll
                    for (int j = 0; j < 10; ++j) {
                        int qq = eq + 4 * j;
                        if (2 * qq < nZ) {
                            int lc = zlc0 + 2 * qq;
                            float v0 = Cr[lc] + bb[lc];
                            float v1 = Cr[lc + 1] + bb[lc + 1];
                            v0 = v0 > 0.f ? v0 : 0.f;
                            v1 = v1 > 0.f ? v1 : 0.f;
                            store_frag_pair(g_zfrag, t & 1, grow, cb + lc - 2048, v0, v1);
                        }
                    }
                }
            }
            gbar(t);
        }
    } else {
        // ---- y-CTAs (HMMA): y(t-1) = z(t-1) @ W2^T + b2 ----
        const int rblk = ct - 128, rbY = rblk * 64;
        const int lane = tid & 31, wid = tid >> 5;
        const int wr = wid >> 1, kh = wid & 1;          // row strip, K half
        u32* w2s = (u32*)smf;                           // 8192 u32
        float* yD = smf + 8192;                         // [2][64][17]
        for (int i = tid; i < 8192; i += 256) w2s[i] = g_W2frag[i];
        __syncthreads();

        const int r0 = wr * 16 + (lane >> 2);
        const int c0 = (lane & 3) * 2;
        float* myD = yD + kh * 1088;

        for (int t = 1; t <= 327; ++t) {
            if (t >= 2) {
                const int buf = (t - 1) & 1;
                const uint4* AH = (const uint4*)g_zfrag
                    + ((((u32)(buf * 2 + 0) * 4 + rblk) * 4 + wr) * 32 + kh * 16) * 32 + lane;
                const uint4* AL = (const uint4*)g_zfrag
                    + ((((u32)(buf * 2 + 1) * 4 + rblk) * 4 + wr) * 32 + kh * 16) * 32 + lane;
                float acc[2][4];
#pragma unroll
                for (int nt = 0; nt < 2; ++nt)
#pragma unroll
                    for (int i = 0; i < 4; ++i) acc[nt][i] = 0.f;

                uint4 pH[2], pL[2];
                pH[0] = __ldcg(AH);        pL[0] = __ldcg(AL);
                pH[1] = __ldcg(AH + 32);   pL[1] = __ldcg(AL + 32);
#pragma unroll
                for (int kgl = 0; kgl < 16; ++kgl) {
                    uint4 aH = pH[kgl & 1], aL = pL[kgl & 1];
                    if (kgl < 14) {
                        pH[kgl & 1] = __ldcg(AH + (kgl + 2) * 32);
                        pL[kgl & 1] = __ldcg(AL + (kgl + 2) * 32);
                    }
                    const int kg = kh * 16 + kgl;
#pragma unroll
                    for (int nt = 0; nt < 2; ++nt) {
                        const u32 bi = kg * 128 + nt * 64 + lane * 2;
                        u32 bH0 = w2s[bi], bH1 = w2s[bi + 1];
                        u32 bL0 = w2s[4096 + bi], bL1 = w2s[4096 + bi + 1];
                        mma16816(acc[nt], aH.x, aH.y, aH.z, aH.w, bH0, bH1);
                        mma16816(acc[nt], aH.x, aH.y, aH.z, aH.w, bL0, bL1);
                        mma16816(acc[nt], aL.x, aL.y, aL.z, aL.w, bH0, bH1);
                    }
                }
#pragma unroll
                for (int nt = 0; nt < 2; ++nt) {
                    int c = nt * 8 + c0;
                    myD[r0 * 17 + c]            = acc[nt][0];
                    myD[r0 * 17 + c + 1]        = acc[nt][1];
                    myD[(r0 + 8) * 17 + c]      = acc[nt][2];
                    myD[(r0 + 8) * 17 + c + 1]  = acc[nt][3];
                }
                __syncthreads();
#pragma unroll
                for (int pi = 0; pi < 3; ++pi) {
                    int p = tid + pi * 256;
                    if (p < 576) {
                        int rw = p / 9, o = p - rw * 9;
                        float v = yD[rw * 17 + o] + yD[1088 + rw * 17 + o] + __ldg(&b2[o]);
                        out[(rbY + rw) * 2934 + (t - 2) * 9 + o] = v;
                    }
                }
            }
            gbar(t);
        }
    }
}

// ---------------- launch -------------------------------------------------------
extern "C" void kernel_launch(void* const* d_in, const int* in_sizes, int n_in,
                              void* d_out, int out_size) {
    const float* x   = (const float*)d_in[0];
    const float* hx0 = (const float*)d_in[1];
    const float* cx0 = (const float*)d_in[2];
    const float* Wih = (const float*)d_in[3];
    const float* Whh = (const float*)d_in[4];
    const float* bih = (const float*)d_in[5];
    const float* bhh = (const float*)d_in[6];
    const float* W1  = (const float*)d_in[7];
    const float* b1  = (const float*)d_in[8];
    const float* W2  = (const float*)d_in[9];
    const float* b2  = (const float*)d_in[10];
    float* out = (float*)d_out;

    cudaFuncSetAttribute(main_kernel, cudaFuncAttributeMaxDynamicSharedMemorySize, SMEM_BYTES);

    prepB<<<10, 256>>>(bih, bhh, b1);
    prepW2frag<<<32, 256>>>(W2);
    prepWfrag<<<5120, 256>>>(Wih, Whh, W1);
    step0_kernel<<<128, 256>>>(x, hx0, cx0, Wih, Whh);
    main_kernel<<<NCTA, 256, SMEM_BYTES>>>(out, b2);
}

// round 16
// speedup vs baseline: 1.4395x; 1.4395x over previous
#include <cuda_runtime.h>
#include <cuda_bf16.h>
#include <math.h>

typedef unsigned long long ull;
typedef unsigned int u32;
typedef unsigned short u16;

#define NCTA 132                 // 128 compute + 4 head
// dynamic smem float offsets (compute CTAs)
#define OFF_C_F  40960           // C tile (64 x 82)
#define OFF_BS_F 46208           // 80 bias floats
#define SMEM_BYTES 185344

// ---------------- persistent device state (no allocations) -----------------
// W fragments interleaved: [((cs*10+ti)*32+kg)*32+lane][4] = {bH0,bH1,bL0,bL1}
__device__ u32 g_Wcomb[1310720];
// h and z in A-fragment layout: [buf][split][rblk][wr][kg][lane][4 u32]
__device__ u32 g_hfrag[2 * 2 * 4 * 4 * 32 * 32 * 4];
__device__ u32 g_zfrag[2 * 2 * 4 * 4 * 32 * 32 * 4];
// W2 B-fragments: [split][kg][nt][lane][2 u32]  (n padded 9->16)
__device__ u32 g_W2frag[8192];
__device__ float g_ball[2560];                     // gate cols j'=4u+g, then b1
__device__ float g_c[256 * 512];
__device__ unsigned g_arrive;
__device__ unsigned g_epoch;

// ---------------- helpers ----------------------------------------------------
__device__ __forceinline__ float fsig(float x) {
    return __fdividef(1.f, 1.f + __expf(-x));
}
__device__ __forceinline__ float ftanh(float x) {
    return 2.f * fsig(2.f * x) - 1.f;
}
__device__ __forceinline__ void split_bf16(float v, __nv_bfloat16& hi, __nv_bfloat16& lo) {
    hi = __float2bfloat16_rn(v);
    lo = __float2bfloat16_rn(v - __bfloat162float(hi));
}

// fence-free grid barrier: acq_rel atomics only (no membar.gpu / L1 flush)
__device__ __forceinline__ void gbar(int p) {
    __syncthreads();
    if (threadIdx.x == 0) {
        u32 prev;
        asm volatile("atom.acq_rel.gpu.global.add.u32 %0, [%1], %2;"
                     : "=r"(prev) : "l"(&g_arrive), "r"(1u) : "memory");
        if (prev == NCTA - 1) {
            asm volatile("st.relaxed.gpu.global.u32 [%0], %1;"
                         :: "l"(&g_arrive), "r"(0u) : "memory");
            asm volatile("st.release.gpu.global.u32 [%0], %1;"
                         :: "l"(&g_epoch), "r"((u32)p) : "memory");
        } else {
            u32 e;
            do {
                asm volatile("ld.acquire.gpu.global.u32 %0, [%1];"
                             : "=r"(e) : "l"(&g_epoch) : "memory");
            } while (e < (u32)p);
        }
    }
    __syncthreads();
}

__device__ __forceinline__ void mma16816(float* d, u32 a0, u32 a1, u32 a2, u32 a3,
                                         u32 b0, u32 b1) {
    asm volatile("mma.sync.aligned.m16n8k16.row.col.f32.bf16.bf16.f32 "
                 "{%0,%1,%2,%3},{%4,%5,%6,%7},{%8,%9},{%0,%1,%2,%3};"
                 : "+f"(d[0]), "+f"(d[1]), "+f"(d[2]), "+f"(d[3])
                 : "r"(a0), "r"(a1), "r"(a2), "r"(a3), "r"(b0), "r"(b1));
}

// write value(fp32) into A-fragment layout (hi and lo splits), single element
__device__ __forceinline__ void store_frag(u32* fragbase, int buf, int row, int u, float v) {
    int rblk = row >> 6, rl = row & 63;
    int wr = rl >> 4, rloc = rl & 15;
    int kg = u >> 4, kkl = u & 15;
    int lane = (rloc & 7) * 4 + ((kkl & 7) >> 1);
    int reg = ((kkl >> 3) & 1) * 2 + ((rloc >> 3) & 1);
    int half = kkl & 1;
    __nv_bfloat16 hi, lo; split_bf16(v, hi, lo);
    u32 idxH = ((((u32)(buf * 2 + 0) * 4 + rblk) * 4 + wr) * 32 + kg) * 128 + lane * 4 + reg;
    u32 idxL = ((((u32)(buf * 2 + 1) * 4 + rblk) * 4 + wr) * 32 + kg) * 128 + lane * 4 + reg;
    ((u16*)fragbase)[idxH * 2 + half] = __bfloat16_as_ushort(hi);
    ((u16*)fragbase)[idxL * 2 + half] = __bfloat16_as_ushort(lo);
}

// paired store: u0 even; writes (u0, u0+1) as one u32 per split
// buf/split stride = 4*4*32*128 = 65536 u32
__device__ __forceinline__ void store_frag_pair(u32* fragbase, int buf, int row, int u0,
                                                float v0, float v1) {
    int rblk = row >> 6, rl = row & 63;
    int wr = rl >> 4, rloc = rl & 15;
    int kg = u0 >> 4, kkl = u0 & 15;          // kkl even
    int lane = (rloc & 7) * 4 + ((kkl & 7) >> 1);
    int reg = ((kkl >> 3) & 1) * 2 + ((rloc >> 3) & 1);
    __nv_bfloat16 h0, l0, h1, l1;
    split_bf16(v0, h0, l0); split_bf16(v1, h1, l1);
    u32 hv = (u32)__bfloat16_as_ushort(h0) | ((u32)__bfloat16_as_ushort(h1) << 16);
    u32 lv = (u32)__bfloat16_as_ushort(l0) | ((u32)__bfloat16_as_ushort(l1) << 16);
    u32 base = (((u32)rblk * 4 + wr) * 32 + kg) * 128 + lane * 4 + reg;
    fragbase[(u32)(buf * 2 + 0) * 65536 + base] = hv;
    fragbase[(u32)(buf * 2 + 1) * 65536 + base] = lv;
}

// ---------------- prep kernels -----------------------------------------------
__device__ __forceinline__ float wall_val(const float* Wih, const float* Whh,
                                          const float* W1, int cs, int k) {
    if (cs < 2048) { int j = (cs & 3) * 512 + (cs >> 2);
                     return Wih[j * 512 + k] + Whh[j * 512 + k]; }
    return W1[(cs - 2048) * 512 + k];
}
__global__ void prepWfrag(const float* __restrict__ Wih, const float* __restrict__ Whh,
                          const float* __restrict__ W1) {
    int gid = blockIdx.x * 256 + threadIdx.x;       // 1,310,720 u32 entries
    int e = gid & 3;
    int lane = (gid >> 2) & 31;
    int kg = (gid >> 7) & 31;
    int rem = gid >> 12;                            // cs*10+ti
    int ti = rem % 10, cs = rem / 10;
    int col = cs * 80 + ti * 8 + (lane >> 2);
    int reg = e & 1, split = e >> 1;
    int k0 = kg * 16 + (lane & 3) * 2 + reg * 8;
    float v0 = wall_val(Wih, Whh, W1, col, k0);
    float v1 = wall_val(Wih, Whh, W1, col, k0 + 1);
    __nv_bfloat16 h0, l0, h1, l1;
    split_bf16(v0, h0, l0); split_bf16(v1, h1, l1);
    u32 val;
    if (split == 0)
        val = (u32)__bfloat16_as_ushort(h0) | ((u32)__bfloat16_as_ushort(h1) << 16);
    else
        val = (u32)__bfloat16_as_ushort(l0) | ((u32)__bfloat16_as_ushort(l1) << 16);
    g_Wcomb[gid] = val;
}
__global__ void prepW2frag(const float* __restrict__ W2) {
    int gid = blockIdx.x * 256 + threadIdx.x;       // 8192
    int reg = gid & 1, lane = (gid >> 1) & 31;
    int nt = (gid >> 6) & 1, kg = (gid >> 7) & 31, split = (gid >> 12) & 1;
    int n = nt * 8 + (lane >> 2);
    int k0 = kg * 16 + (lane & 3) * 2 + reg * 8;
    float v0 = (n < 9) ? W2[n * 512 + k0] : 0.f;
    float v1 = (n < 9) ? W2[n * 512 + k0 + 1] : 0.f;
    __nv_bfloat16 h0, l0, h1, l1;
    split_bf16(v0, h0, l0); split_bf16(v1, h1, l1);
    u32 val;
    if (split == 0)
        val = (u32)__bfloat16_as_ushort(h0) | ((u32)__bfloat16_as_ushort(h1) << 16);
    else
        val = (u32)__bfloat16_as_ushort(l0) | ((u32)__bfloat16_as_ushort(l1) << 16);
    g_W2frag[gid] = val;
}
__global__ void prepB(const float* __restrict__ bih, const float* __restrict__ bhh,
                      const float* __restrict__ b1) {
    int idx = blockIdx.x * 256 + threadIdx.x;       // 2560
    if (idx < 2048) { int u = idx >> 2, gi = idx & 3, j = gi * 512 + u;
                      g_ball[idx] = bih[j] + bhh[j]; }
    else if (idx < 2560) g_ball[idx] = b1[idx - 2048];
    if (idx == 0) { g_arrive = 0; g_epoch = 0; }
}

// ---------------- step 0: h(1), c(1) = cell(x, hx0, cx0), K=1024 --------------
__global__ void __launch_bounds__(256) step0_kernel(
    const float* __restrict__ x, const float* __restrict__ hx0,
    const float* __restrict__ cx0,
    const float* __restrict__ Wih, const float* __restrict__ Whh) {
    __shared__ __align__(16) float As[32 * 64];
    __shared__ __align__(16) float Wsm[32 * 64];
    const int tid = threadIdx.x, tx = tid & 15, ty = tid >> 4;
    const int ct = blockIdx.x, rb = (ct >> 5) << 6, cb = (ct & 31) << 6;
    const int r = tid & 63, s = tid >> 6;
    const int jc = cb + r, jrow = (jc & 3) * 512 + (jc >> 2);

    float acc[4][4] = {};
    for (int kc = 0; kc < 1024; kc += 32) {
        const float* Asrc = (kc < 512) ? x : hx0;
        const float* Wsrc = (kc < 512) ? Wih : Whh;
        const int kloc = (kc < 512) ? kc : kc - 512;
        __syncthreads();
#pragma unroll
        for (int h = 0; h < 2; ++h) {
            int sl = s + h * 4;
            float4 v = *(const float4*)(Asrc + (rb + r) * 512 + kloc + sl * 4);
            As[(sl * 4 + 0) * 64 + r] = v.x; As[(sl * 4 + 1) * 64 + r] = v.y;
            As[(sl * 4 + 2) * 64 + r] = v.z; As[(sl * 4 + 3) * 64 + r] = v.w;
            float4 w = *(const float4*)(Wsrc + jrow * 512 + kloc + sl * 4);
            Wsm[(sl * 4 + 0) * 64 + r] = w.x; Wsm[(sl * 4 + 1) * 64 + r] = w.y;
            Wsm[(sl * 4 + 2) * 64 + r] = w.z; Wsm[(sl * 4 + 3) * 64 + r] = w.w;
        }
        __syncthreads();
#pragma unroll 8
        for (int k = 0; k < 32; ++k) {
            float a0 = As[k * 64 + ty * 4 + 0], a1 = As[k * 64 + ty * 4 + 1];
            float a2 = As[k * 64 + ty * 4 + 2], a3 = As[k * 64 + ty * 4 + 3];
            float w0 = Wsm[k * 64 + tx * 4 + 0], w1 = Wsm[k * 64 + tx * 4 + 1];
            float w2 = Wsm[k * 64 + tx * 4 + 2], w3 = Wsm[k * 64 + tx * 4 + 3];
            acc[0][0] += a0 * w0; acc[0][1] += a0 * w1; acc[0][2] += a0 * w2; acc[0][3] += a0 * w3;
            acc[1][0] += a1 * w0; acc[1][1] += a1 * w1; acc[1][2] += a1 * w2; acc[1][3] += a1 * w3;
            acc[2][0] += a2 * w0; acc[2][1] += a2 * w1; acc[2][2] += a2 * w2; acc[2][3] += a2 * w3;
            acc[3][0] += a3 * w0; acc[3][1] += a3 * w1; acc[3][2] += a3 * w2; acc[3][3] += a3 * w3;
        }
    }
    const int u = (cb >> 2) + tx;
#pragma unroll
    for (int i = 0; i < 4; ++i) {
        int row = rb + ty * 4 + i;
        int gx = row * 512 + u;
        float vi = fsig(acc[i][0] + g_ball[cb + tx * 4 + 0]);
        float vf = fsig(acc[i][1] + g_ball[cb + tx * 4 + 1]);
        float vg = ftanh(acc[i][2] + g_ball[cb + tx * 4 + 2]);
        float vo = fsig(acc[i][3] + g_ball[cb + tx * 4 + 3]);
        float cn = vf * cx0[gx] + vi * vg;
        g_c[gx] = cn;
        store_frag(g_hfrag, 1, row, u, vo * ftanh(cn));
    }
}

// ---------------- persistent main kernel --------------------------------------
__global__ void __launch_bounds__(256, 1) main_kernel(float* __restrict__ out,
                                                      const float* __restrict__ b2) {
    extern __shared__ __align__(16) float smf[];
    const int tid = threadIdx.x, ct = blockIdx.x;

    if (ct < 128) {
        const int rblk = ct >> 5, rb = rblk << 6, cs = ct & 31, cb = cs * 80;
        const int lane = tid & 31, wid = tid >> 5;
        const int wr = wid & 3, wc = wid >> 2;          // warp: rows wr*16, cols wc*40
        const int ti0 = wc * 5;
        const int nU   = (cs < 25) ? 20 : (cs == 25 ? 12 : 0);
        const int zlc0 = (cs < 25) ? 80 : (cs == 25 ? 48 : 0);
        const int nZ = 80 - zlc0;
        const int nP = nU >> 1;                          // gate unit pairs
        const int erow = tid >> 2, eq = tid & 3, ub = cb >> 2;

        // one-time: resident W fragments (interleaved hi/lo), 160KB
        {
            const uint4* src = (const uint4*)(g_Wcomb + cs * 40960);
            uint4* dst = (uint4*)smf;
#pragma unroll
            for (int i = 0; i < 40; ++i) dst[tid + i * 256] = src[tid + i * 256];
        }
        if (tid < 80) smf[OFF_BS_F + tid] = g_ball[cb + tid];
        __syncthreads();

        const uint4* wsm = (const uint4*)smf;

        for (int t = 1; t <= 327; ++t) {
            const bool isGate = nU > 0, hasZ = nZ > 0;
            if (t <= 326 && ((t <= 325 && isGate) || hasZ)) {
                float accH[5][4], accL[5][4];
#pragma unroll
                for (int j = 0; j < 5; ++j)
#pragma unroll
                    for (int i = 0; i < 4; ++i) { accH[j][i] = 0.f; accL[j][i] = 0.f; }

                const int buf = t & 1;
                const uint4* AH = (const uint4*)g_hfrag
                    + (((u32)(buf * 2 + 0) * 4 + rblk) * 4 + wr) * 1024 + lane;
                const uint4* AL = (const uint4*)g_hfrag
                    + (((u32)(buf * 2 + 1) * 4 + rblk) * 4 + wr) * 1024 + lane;

                uint4 pH[2], pL[2];
                pH[0] = __ldcg(AH);          pL[0] = __ldcg(AL);
                pH[1] = __ldcg(AH + 32);     pL[1] = __ldcg(AL + 32);

#pragma unroll
                for (int kg = 0; kg < 32; ++kg) {
                    uint4 aH = pH[kg & 1], aL = pL[kg & 1];
                    if (kg < 30) {
                        pH[kg & 1] = __ldcg(AH + (kg + 2) * 32);
                        pL[kg & 1] = __ldcg(AL + (kg + 2) * 32);
                    }
#pragma unroll
                    for (int j = 0; j < 5; ++j) {
                        uint4 w = wsm[((ti0 + j) * 32 + kg) * 32 + lane];
                        mma16816(accH[j], aH.x, aH.y, aH.z, aH.w, w.x, w.y);
                        mma16816(accL[j], aH.x, aH.y, aH.z, aH.w, w.z, w.w);
                        mma16816(accL[j], aL.x, aL.y, aL.z, aL.w, w.x, w.y);
                    }
                }
                // D fragments -> C tile in smem (stride 82 floats)
                {
                    const int drow = wr * 16 + (lane >> 2);
                    const int dcol = wc * 40 + (lane & 3) * 2;
                    float* C0 = smf + OFF_C_F + drow * 82 + dcol;
                    float* C1 = smf + OFF_C_F + (drow + 8) * 82 + dcol;
#pragma unroll
                    for (int j = 0; j < 5; ++j) {
                        *(float2*)(C0 + j * 8) =
                            make_float2(accH[j][0] + accL[j][0], accH[j][1] + accL[j][1]);
                        *(float2*)(C1 + j * 8) =
                            make_float2(accH[j][2] + accL[j][2], accH[j][3] + accL[j][3]);
                    }
                }
                __syncthreads();

                const float* Cr = smf + OFF_C_F + erow * 82;
                const float* bb = smf + OFF_BS_F;
                const int grow = rb + erow;
                if (t <= 325 && isGate) {
                    const int nbuf = (t + 1) & 1;
#pragma unroll
                    for (int j = 0; j < 3; ++j) {
                        int pp = eq + 4 * j;
                        if (pp < nP) {
                            int lc = pp * 8;
                            int u0 = ub + 2 * pp;
                            float2 cc = *(float2*)(g_c + grow * 512 + u0);
                            float vi0 = fsig(Cr[lc + 0] + bb[lc + 0]);
                            float vf0 = fsig(Cr[lc + 1] + bb[lc + 1]);
                            float vg0 = ftanh(Cr[lc + 2] + bb[lc + 2]);
                            float vo0 = fsig(Cr[lc + 3] + bb[lc + 3]);
                            float vi1 = fsig(Cr[lc + 4] + bb[lc + 4]);
                            float vf1 = fsig(Cr[lc + 5] + bb[lc + 5]);
                            float vg1 = ftanh(Cr[lc + 6] + bb[lc + 6]);
                            float vo1 = fsig(Cr[lc + 7] + bb[lc + 7]);
                            float cn0 = vf0 * cc.x + vi0 * vg0;
                            float cn1 = vf1 * cc.y + vi1 * vg1;
                            *(float2*)(g_c + grow * 512 + u0) = make_float2(cn0, cn1);
                            store_frag_pair(g_hfrag, nbuf, grow, u0,
                                            vo0 * ftanh(cn0), vo1 * ftanh(cn1));
                        }
                    }
                }
                if (hasZ) {
#pragma unroll
                    for (int j = 0; j < 10; ++j) {
                        int qq = eq + 4 * j;
                        if (2 * qq < nZ) {
                            int lc = zlc0 + 2 * qq;
                            float v0 = Cr[lc] + bb[lc];
                            float v1 = Cr[lc + 1] + bb[lc + 1];
                            v0 = v0 > 0.f ? v0 : 0.f;
                            v1 = v1 > 0.f ? v1 : 0.f;
                            store_frag_pair(g_zfrag, t & 1, grow, cb + lc - 2048, v0, v1);
                        }
                    }
                }
            }
            gbar(t);
        }
    } else {
        // ---- y-CTAs (HMMA): y(t-1) = z(t-1) @ W2^T + b2 ----
        const int rblk = ct - 128, rbY = rblk * 64;
        const int lane = tid & 31, wid = tid >> 5;
        const int wr = wid >> 1, kh = wid & 1;          // row strip, K half
        u32* w2s = (u32*)smf;                           // 8192 u32
        float* yD = smf + 8192;                         // [2][64][17]
        for (int i = tid; i < 8192; i += 256) w2s[i] = g_W2frag[i];
        __syncthreads();

        const int r0 = wr * 16 + (lane >> 2);
        const int c0 = (lane & 3) * 2;
        float* myD = yD + kh * 1088;

        for (int t = 1; t <= 327; ++t) {
            if (t >= 2) {
                const int buf = (t - 1) & 1;
                const uint4* AH = (const uint4*)g_zfrag
                    + ((((u32)(buf * 2 + 0) * 4 + rblk) * 4 + wr) * 32 + kh * 16) * 32 + lane;
                const uint4* AL = (const uint4*)g_zfrag
                    + ((((u32)(buf * 2 + 1) * 4 + rblk) * 4 + wr) * 32 + kh * 16) * 32 + lane;
                float acc[2][4];
#pragma unroll
                for (int nt = 0; nt < 2; ++nt)
#pragma unroll
                    for (int i = 0; i < 4; ++i) acc[nt][i] = 0.f;

                uint4 pH[2], pL[2];
                pH[0] = __ldcg(AH);        pL[0] = __ldcg(AL);
                pH[1] = __ldcg(AH + 32);   pL[1] = __ldcg(AL + 32);
#pragma unroll
                for (int kgl = 0; kgl < 16; ++kgl) {
                    uint4 aH = pH[kgl & 1], aL = pL[kgl & 1];
                    if (kgl < 14) {
                        pH[kgl & 1] = __ldcg(AH + (kgl + 2) * 32);
                        pL[kgl & 1] = __ldcg(AL + (kgl + 2) * 32);
                    }
                    const int kg = kh * 16 + kgl;
#pragma unroll
                    for (int nt = 0; nt < 2; ++nt) {
                        const u32 bi = kg * 128 + nt * 64 + lane * 2;
                        u32 bH0 = w2s[bi], bH1 = w2s[bi + 1];
                        u32 bL0 = w2s[4096 + bi], bL1 = w2s[4096 + bi + 1];
                        mma16816(acc[nt], aH.x, aH.y, aH.z, aH.w, bH0, bH1);
                        mma16816(acc[nt], aH.x, aH.y, aH.z, aH.w, bL0, bL1);
                        mma16816(acc[nt], aL.x, aL.y, aL.z, aL.w, bH0, bH1);
                    }
                }
#pragma unroll
                for (int nt = 0; nt < 2; ++nt) {
                    int c = nt * 8 + c0;
                    myD[r0 * 17 + c]            = acc[nt][0];
                    myD[r0 * 17 + c + 1]        = acc[nt][1];
                    myD[(r0 + 8) * 17 + c]      = acc[nt][2];
                    myD[(r0 + 8) * 17 + c + 1]  = acc[nt][3];
                }
                __syncthreads();
#pragma unroll
                for (int pi = 0; pi < 3; ++pi) {
                    int p = tid + pi * 256;
                    if (p < 576) {
                        int rw = p / 9, o = p - rw * 9;
                        float v = yD[rw * 17 + o] + yD[1088 + rw * 17 + o] + __ldg(&b2[o]);
                        out[(rbY + rw) * 2934 + (t - 2) * 9 + o] = v;
                    }
                }
            }
            gbar(t);
        }
    }
}

// ---------------- launch -------------------------------------------------------
extern "C" void kernel_launch(void* const* d_in, const int* in_sizes, int n_in,
                              void* d_out, int out_size) {
    const float* x   = (const float*)d_in[0];
    const float* hx0 = (const float*)d_in[1];
    const float* cx0 = (const float*)d_in[2];
    const float* Wih = (const float*)d_in[3];
    const float* Whh = (const float*)d_in[4];
    const float* bih = (const float*)d_in[5];
    const float* bhh = (const float*)d_in[6];
    const float* W1  = (const float*)d_in[7];
    const float* b1  = (const float*)d_in[8];
    const float* W2  = (const float*)d_in[9];
    const float* b2  = (const float*)d_in[10];
    float* out = (float*)d_out;

    cudaFuncSetAttribute(main_kernel, cudaFuncAttributeMaxDynamicSharedMemorySize, SMEM_BYTES);

    prepB<<<10, 256>>>(bih, bhh, b1);
    prepW2frag<<<32, 256>>>(W2);
    prepWfrag<<<5120, 256>>>(Wih, Whh, W1);
    step0_kernel<<<128, 256>>>(x, hx0, cx0, Wih, Whh);
    main_kernel<<<NCTA, 256, SMEM_BYTES>>>(out, b2);
}

// round 17
// speedup vs baseline: 1.4521x; 1.0087x over previous
#include <cuda_runtime.h>
#include <cuda_bf16.h>
#include <math.h>

typedef unsigned long long ull;
typedef unsigned int u32;
typedef unsigned short u16;

#define NCTA 132                 // 128 compute + 4 head
// dynamic smem float offsets (compute CTAs)
#define OFF_C_F  40960           // C tile (64 x 82)
#define OFF_BS_F 46208           // 80 bias floats
#define SMEM_BYTES 185344

// ---------------- persistent device state (no allocations) -----------------
// W fragments interleaved: [((cs*10+ti)*32+kg)*32+lane][4] = {bH0,bH1,bL0,bL1}
__device__ u32 g_Wcomb[1310720];
// h and z in A-fragment layout: [buf][split][rblk][wr][kg][lane][4 u32]
__device__ u32 g_hfrag[2 * 2 * 4 * 4 * 32 * 32 * 4];
__device__ u32 g_zfrag[2 * 2 * 4 * 4 * 32 * 32 * 4];
// W2 B-fragments: [split][kg][nt][lane][2 u32]  (n padded 9->16)
__device__ u32 g_W2frag[8192];
__device__ float g_ball[2560];                     // gate cols j'=4u+g, then b1
__device__ float g_c[256 * 512];
__device__ unsigned g_arrive;
__device__ unsigned g_epoch;

// ---------------- helpers ----------------------------------------------------
__device__ __forceinline__ float fsig(float x) {
    return __fdividef(1.f, 1.f + __expf(-x));
}
__device__ __forceinline__ float ftanh(float x) {
    return 2.f * fsig(2.f * x) - 1.f;
}
__device__ __forceinline__ void split_bf16(float v, __nv_bfloat16& hi, __nv_bfloat16& lo) {
    hi = __float2bfloat16_rn(v);
    lo = __float2bfloat16_rn(v - __bfloat162float(hi));
}

// fence-free grid barrier: acq_rel atomics only (no membar.gpu / L1 flush)
__device__ __forceinline__ void gbar(int p) {
    __syncthreads();
    if (threadIdx.x == 0) {
        u32 prev;
        asm volatile("atom.acq_rel.gpu.global.add.u32 %0, [%1], %2;"
                     : "=r"(prev) : "l"(&g_arrive), "r"(1u) : "memory");
        if (prev == NCTA - 1) {
            asm volatile("st.relaxed.gpu.global.u32 [%0], %1;"
                         :: "l"(&g_arrive), "r"(0u) : "memory");
            asm volatile("st.release.gpu.global.u32 [%0], %1;"
                         :: "l"(&g_epoch), "r"((u32)p) : "memory");
        } else {
            u32 e;
            do {
                asm volatile("ld.acquire.gpu.global.u32 %0, [%1];"
                             : "=r"(e) : "l"(&g_epoch) : "memory");
            } while (e < (u32)p);
        }
    }
    __syncthreads();
}

__device__ __forceinline__ void mma16816(float* d, u32 a0, u32 a1, u32 a2, u32 a3,
                                         u32 b0, u32 b1) {
    asm volatile("mma.sync.aligned.m16n8k16.row.col.f32.bf16.bf16.f32 "
                 "{%0,%1,%2,%3},{%4,%5,%6,%7},{%8,%9},{%0,%1,%2,%3};"
                 : "+f"(d[0]), "+f"(d[1]), "+f"(d[2]), "+f"(d[3])
                 : "r"(a0), "r"(a1), "r"(a2), "r"(a3), "r"(b0), "r"(b1));
}

// write value(fp32) into A-fragment layout (hi and lo splits), single element
__device__ __forceinline__ void store_frag(u32* fragbase, int buf, int row, int u, float v) {
    int rblk = row >> 6, rl = row & 63;
    int wr = rl >> 4, rloc = rl & 15;
    int kg = u >> 4, kkl = u & 15;
    int lane = (rloc & 7) * 4 + ((kkl & 7) >> 1);
    int reg = ((kkl >> 3) & 1) * 2 + ((rloc >> 3) & 1);
    int half = kkl & 1;
    __nv_bfloat16 hi, lo; split_bf16(v, hi, lo);
    u32 idxH = ((((u32)(buf * 2 + 0) * 4 + rblk) * 4 + wr) * 32 + kg) * 128 + lane * 4 + reg;
    u32 idxL = ((((u32)(buf * 2 + 1) * 4 + rblk) * 4 + wr) * 32 + kg) * 128 + lane * 4 + reg;
    ((u16*)fragbase)[idxH * 2 + half] = __bfloat16_as_ushort(hi);
    ((u16*)fragbase)[idxL * 2 + half] = __bfloat16_as_ushort(lo);
}

// paired store: u0 even; writes (u0, u0+1) as one u32 per split
// buf/split stride = 4*4*32*128 = 65536 u32
__device__ __forceinline__ void store_frag_pair(u32* fragbase, int buf, int row, int u0,
                                                float v0, float v1) {
    int rblk = row >> 6, rl = row & 63;
    int wr = rl >> 4, rloc = rl & 15;
    int kg = u0 >> 4, kkl = u0 & 15;          // kkl even
    int lane = (rloc & 7) * 4 + ((kkl & 7) >> 1);
    int reg = ((kkl >> 3) & 1) * 2 + ((rloc >> 3) & 1);
    __nv_bfloat16 h0, l0, h1, l1;
    split_bf16(v0, h0, l0); split_bf16(v1, h1, l1);
    u32 hv = (u32)__bfloat16_as_ushort(h0) | ((u32)__bfloat16_as_ushort(h1) << 16);
    u32 lv = (u32)__bfloat16_as_ushort(l0) | ((u32)__bfloat16_as_ushort(l1) << 16);
    u32 base = (((u32)rblk * 4 + wr) * 32 + kg) * 128 + lane * 4 + reg;
    fragbase[(u32)(buf * 2 + 0) * 65536 + base] = hv;
    fragbase[(u32)(buf * 2 + 1) * 65536 + base] = lv;
}

// ---------------- prep kernels -----------------------------------------------
__device__ __forceinline__ float wall_val(const float* Wih, const float* Whh,
                                          const float* W1, int cs, int k) {
    if (cs < 2048) { int j = (cs & 3) * 512 + (cs >> 2);
                     return Wih[j * 512 + k] + Whh[j * 512 + k]; }
    return W1[(cs - 2048) * 512 + k];
}
__global__ void prepWfrag(const float* __restrict__ Wih, const float* __restrict__ Whh,
                          const float* __restrict__ W1) {
    int gid = blockIdx.x * 256 + threadIdx.x;       // 1,310,720 u32 entries
    int e = gid & 3;
    int lane = (gid >> 2) & 31;
    int kg = (gid >> 7) & 31;
    int rem = gid >> 12;                            // cs*10+ti
    int ti = rem % 10, cs = rem / 10;
    int col = cs * 80 + ti * 8 + (lane >> 2);
    int reg = e & 1, split = e >> 1;
    int k0 = kg * 16 + (lane & 3) * 2 + reg * 8;
    float v0 = wall_val(Wih, Whh, W1, col, k0);
    float v1 = wall_val(Wih, Whh, W1, col, k0 + 1);
    __nv_bfloat16 h0, l0, h1, l1;
    split_bf16(v0, h0, l0); split_bf16(v1, h1, l1);
    u32 val;
    if (split == 0)
        val = (u32)__bfloat16_as_ushort(h0) | ((u32)__bfloat16_as_ushort(h1) << 16);
    else
        val = (u32)__bfloat16_as_ushort(l0) | ((u32)__bfloat16_as_ushort(l1) << 16);
    g_Wcomb[gid] = val;
}
__global__ void prepW2frag(const float* __restrict__ W2) {
    int gid = blockIdx.x * 256 + threadIdx.x;       // 8192
    int reg = gid & 1, lane = (gid >> 1) & 31;
    int nt = (gid >> 6) & 1, kg = (gid >> 7) & 31, split = (gid >> 12) & 1;
    int n = nt * 8 + (lane >> 2);
    int k0 = kg * 16 + (lane & 3) * 2 + reg * 8;
    float v0 = (n < 9) ? W2[n * 512 + k0] : 0.f;
    float v1 = (n < 9) ? W2[n * 512 + k0 + 1] : 0.f;
    __nv_bfloat16 h0, l0, h1, l1;
    split_bf16(v0, h0, l0); split_bf16(v1, h1, l1);
    u32 val;
    if (split == 0)
        val = (u32)__bfloat16_as_ushort(h0) | ((u32)__bfloat16_as_ushort(h1) << 16);
    else
        val = (u32)__bfloat16_as_ushort(l0) | ((u32)__bfloat16_as_ushort(l1) << 16);
    g_W2frag[gid] = val;
}
__global__ void prepB(const float* __restrict__ bih, const float* __restrict__ bhh,
                      const float* __restrict__ b1) {
    int idx = blockIdx.x * 256 + threadIdx.x;       // 2560
    if (idx < 2048) { int u = idx >> 2, gi = idx & 3, j = gi * 512 + u;
                      g_ball[idx] = bih[j] + bhh[j]; }
    else if (idx < 2560) g_ball[idx] = b1[idx - 2048];
    if (idx == 0) { g_arrive = 0; g_epoch = 0; }
}

// ---------------- step 0: h(1), c(1) = cell(x, hx0, cx0), K=1024 --------------
__global__ void __launch_bounds__(256) step0_kernel(
    const float* __restrict__ x, const float* __restrict__ hx0,
    const float* __restrict__ cx0,
    const float* __restrict__ Wih, const float* __restrict__ Whh) {
    __shared__ __align__(16) float As[32 * 64];
    __shared__ __align__(16) float Wsm[32 * 64];
    const int tid = threadIdx.x, tx = tid & 15, ty = tid >> 4;
    const int ct = blockIdx.x, rb = (ct >> 5) << 6, cb = (ct & 31) << 6;
    const int r = tid & 63, s = tid >> 6;
    const int jc = cb + r, jrow = (jc & 3) * 512 + (jc >> 2);

    float acc[4][4] = {};
    for (int kc = 0; kc < 1024; kc += 32) {
        const float* Asrc = (kc < 512) ? x : hx0;
        const float* Wsrc = (kc < 512) ? Wih : Whh;
        const int kloc = (kc < 512) ? kc : kc - 512;
        __syncthreads();
#pragma unroll
        for (int h = 0; h < 2; ++h) {
            int sl = s + h * 4;
            float4 v = *(const float4*)(Asrc + (rb + r) * 512 + kloc + sl * 4);
            As[(sl * 4 + 0) * 64 + r] = v.x; As[(sl * 4 + 1) * 64 + r] = v.y;
            As[(sl * 4 + 2) * 64 + r] = v.z; As[(sl * 4 + 3) * 64 + r] = v.w;
            float4 w = *(const float4*)(Wsrc + jrow * 512 + kloc + sl * 4);
            Wsm[(sl * 4 + 0) * 64 + r] = w.x; Wsm[(sl * 4 + 1) * 64 + r] = w.y;
            Wsm[(sl * 4 + 2) * 64 + r] = w.z; Wsm[(sl * 4 + 3) * 64 + r] = w.w;
        }
        __syncthreads();
#pragma unroll 8
        for (int k = 0; k < 32; ++k) {
            float a0 = As[k * 64 + ty * 4 + 0], a1 = As[k * 64 + ty * 4 + 1];
            float a2 = As[k * 64 + ty * 4 + 2], a3 = As[k * 64 + ty * 4 + 3];
            float w0 = Wsm[k * 64 + tx * 4 + 0], w1 = Wsm[k * 64 + tx * 4 + 1];
            float w2 = Wsm[k * 64 + tx * 4 + 2], w3 = Wsm[k * 64 + tx * 4 + 3];
            acc[0][0] += a0 * w0; acc[0][1] += a0 * w1; acc[0][2] += a0 * w2; acc[0][3] += a0 * w3;
            acc[1][0] += a1 * w0; acc[1][1] += a1 * w1; acc[1][2] += a1 * w2; acc[1][3] += a1 * w3;
            acc[2][0] += a2 * w0; acc[2][1] += a2 * w1; acc[2][2] += a2 * w2; acc[2][3] += a2 * w3;
            acc[3][0] += a3 * w0; acc[3][1] += a3 * w1; acc[3][2] += a3 * w2; acc[3][3] += a3 * w3;
        }
    }
    const int u = (cb >> 2) + tx;
#pragma unroll
    for (int i = 0; i < 4; ++i) {
        int row = rb + ty * 4 + i;
        int gx = row * 512 + u;
        float vi = fsig(acc[i][0] + g_ball[cb + tx * 4 + 0]);
        float vf = fsig(acc[i][1] + g_ball[cb + tx * 4 + 1]);
        float vg = ftanh(acc[i][2] + g_ball[cb + tx * 4 + 2]);
        float vo = fsig(acc[i][3] + g_ball[cb + tx * 4 + 3]);
        float cn = vf * cx0[gx] + vi * vg;
        g_c[gx] = cn;
        store_frag(g_hfrag, 1, row, u, vo * ftanh(cn));
    }
}

// ---------------- persistent main kernel --------------------------------------
__global__ void __launch_bounds__(256, 1) main_kernel(float* __restrict__ out,
                                                      const float* __restrict__ b2) {
    extern __shared__ __align__(16) float smf[];
    const int tid = threadIdx.x, ct = blockIdx.x;

    if (ct < 128) {
        const int rblk = ct >> 5, rb = rblk << 6, cs = ct & 31, cb = cs * 80;
        const int lane = tid & 31, wid = tid >> 5;
        const int wr = wid & 3, wc = wid >> 2;          // warp: rows wr*16, cols wc*40
        const int ti0 = wc * 5;
        const int nU   = (cs < 25) ? 20 : (cs == 25 ? 12 : 0);
        const int zlc0 = (cs < 25) ? 80 : (cs == 25 ? 48 : 0);
        const int nZ = 80 - zlc0;
        const int nP = nU >> 1;                          // gate unit pairs
        const int erow = tid >> 2, eq = tid & 3, ub = cb >> 2;

        // one-time: resident W fragments (interleaved hi/lo), 160KB
        {
            const uint4* src = (const uint4*)(g_Wcomb + cs * 40960);
            uint4* dst = (uint4*)smf;
#pragma unroll
            for (int i = 0; i < 40; ++i) dst[tid + i * 256] = src[tid + i * 256];
        }
        if (tid < 80) smf[OFF_BS_F + tid] = g_ball[cb + tid];
        __syncthreads();

        const uint4* wsm = (const uint4*)smf;

        for (int t = 1; t <= 327; ++t) {
            const bool isGate = nU > 0, hasZ = nZ > 0;
            if (t <= 326 && ((t <= 325 && isGate) || hasZ)) {
                float accH[5][4], accL[5][4];
#pragma unroll
                for (int j = 0; j < 5; ++j)
#pragma unroll
                    for (int i = 0; i < 4; ++i) { accH[j][i] = 0.f; accL[j][i] = 0.f; }

                const int buf = t & 1;
                const uint4* AH = (const uint4*)g_hfrag
                    + (((u32)(buf * 2 + 0) * 4 + rblk) * 4 + wr) * 1024 + lane;
                const uint4* AL = (const uint4*)g_hfrag
                    + (((u32)(buf * 2 + 1) * 4 + rblk) * 4 + wr) * 1024 + lane;

                uint4 pH[4], pL[4];
#pragma unroll
                for (int i = 0; i < 4; ++i) {
                    pH[i] = __ldcg(AH + i * 32);
                    pL[i] = __ldcg(AL + i * 32);
                }

#pragma unroll
                for (int kg = 0; kg < 32; ++kg) {
                    uint4 aH = pH[kg & 3], aL = pL[kg & 3];
                    if (kg < 28) {
                        pH[kg & 3] = __ldcg(AH + (kg + 4) * 32);
                        pL[kg & 3] = __ldcg(AL + (kg + 4) * 32);
                    }
#pragma unroll
                    for (int j = 0; j < 5; ++j) {
                        uint4 w = wsm[((ti0 + j) * 32 + kg) * 32 + lane];
                        mma16816(accH[j], aH.x, aH.y, aH.z, aH.w, w.x, w.y);
                        mma16816(accL[j], aH.x, aH.y, aH.z, aH.w, w.z, w.w);
                        mma16816(accL[j], aL.x, aL.y, aL.z, aL.w, w.x, w.y);
                    }
                }
                // D fragments -> C tile in smem (stride 82 floats)
                {
                    const int drow = wr * 16 + (lane >> 2);
                    const int dcol = wc * 40 + (lane & 3) * 2;
                    float* C0 = smf + OFF_C_F + drow * 82 + dcol;
                    float* C1 = smf + OFF_C_F + (drow + 8) * 82 + dcol;
#pragma unroll
                    for (int j = 0; j < 5; ++j) {
                        *(float2*)(C0 + j * 8) =
                            make_float2(accH[j][0] + accL[j][0], accH[j][1] + accL[j][1]);
                        *(float2*)(C1 + j * 8) =
                            make_float2(accH[j][2] + accL[j][2], accH[j][3] + accL[j][3]);
                    }
                }
                __syncthreads();

                const float* Cr = smf + OFF_C_F + erow * 82;
                const float* bb = smf + OFF_BS_F;
                const int grow = rb + erow;
                if (t <= 325 && isGate) {
                    const int nbuf = (t + 1) & 1;
#pragma unroll
                    for (int j = 0; j < 3; ++j) {
                        int pp = eq + 4 * j;
                        if (pp < nP) {
                            int lc = pp * 8;
                            int u0 = ub + 2 * pp;
                            float2 cc = *(float2*)(g_c + grow * 512 + u0);
                            float vi0 = fsig(Cr[lc + 0] + bb[lc + 0]);
                            float vf0 = fsig(Cr[lc + 1] + bb[lc + 1]);
                            float vg0 = ftanh(Cr[lc + 2] + bb[lc + 2]);
                            float vo0 = fsig(Cr[lc + 3] + bb[lc + 3]);
                            float vi1 = fsig(Cr[lc + 4] + bb[lc + 4]);
                            float vf1 = fsig(Cr[lc + 5] + bb[lc + 5]);
                            float vg1 = ftanh(Cr[lc + 6] + bb[lc + 6]);
                            float vo1 = fsig(Cr[lc + 7] + bb[lc + 7]);
                            float cn0 = vf0 * cc.x + vi0 * vg0;
                            float cn1 = vf1 * cc.y + vi1 * vg1;
                            *(float2*)(g_c + grow * 512 + u0) = make_float2(cn0, cn1);
                            store_frag_pair(g_hfrag, nbuf, grow, u0,
                                            vo0 * ftanh(cn0), vo1 * ftanh(cn1));
                        }
                    }
                }
                if (hasZ) {
#pragma unroll
                    for (int j = 0; j < 10; ++j) {
                        int qq = eq + 4 * j;
                        if (2 * qq < nZ) {
                            int lc = zlc0 + 2 * qq;
                            float v0 = Cr[lc] + bb[lc];
                            float v1 = Cr[lc + 1] + bb[lc + 1];
                            v0 = v0 > 0.f ? v0 : 0.f;
                            v1 = v1 > 0.f ? v1 : 0.f;
                            store_frag_pair(g_zfrag, t & 1, grow, cb + lc - 2048, v0, v1);
                        }
                    }
                }
            }
            gbar(t);
        }
    } else {
        // ---- y-CTAs (HMMA): y(t-1) = z(t-1) @ W2^T + b2 ----
        const int rblk = ct - 128, rbY = rblk * 64;
        const int lane = tid & 31, wid = tid >> 5;
        const int wr = wid >> 1, kh = wid & 1;          // row strip, K half
        u32* w2s = (u32*)smf;                           // 8192 u32
        float* yD = smf + 8192;                         // [2][64][17]
        for (int i = tid; i < 8192; i += 256) w2s[i] = g_W2frag[i];
        __syncthreads();

        const int r0 = wr * 16 + (lane >> 2);
        const int c0 = (lane & 3) * 2;
        float* myD = yD + kh * 1088;

        for (int t = 1; t <= 327; ++t) {
            if (t >= 2) {
                const int buf = (t - 1) & 1;
                const uint4* AH = (const uint4*)g_zfrag
                    + ((((u32)(buf * 2 + 0) * 4 + rblk) * 4 + wr) * 32 + kh * 16) * 32 + lane;
                const uint4* AL = (const uint4*)g_zfrag
                    + ((((u32)(buf * 2 + 1) * 4 + rblk) * 4 + wr) * 32 + kh * 16) * 32 + lane;
                float acc[2][4];
#pragma unroll
                for (int nt = 0; nt < 2; ++nt)
#pragma unroll
                    for (int i = 0; i < 4; ++i) acc[nt][i] = 0.f;

                uint4 pH[4], pL[4];
#pragma unroll
                for (int i = 0; i < 4; ++i) {
                    pH[i] = __ldcg(AH + i * 32);
                    pL[i] = __ldcg(AL + i * 32);
                }
#pragma unroll
                for (int kgl = 0; kgl < 16; ++kgl) {
                    uint4 aH = pH[kgl & 3], aL = pL[kgl & 3];
                    if (kgl < 12) {
                        pH[kgl & 3] = __ldcg(AH + (kgl + 4) * 32);
                        pL[kgl & 3] = __ldcg(AL + (kgl + 4) * 32);
                    }
                    const int kg = kh * 16 + kgl;
#pragma unroll
                    for (int nt = 0; nt < 2; ++nt) {
                        const u32 bi = kg * 128 + nt * 64 + lane * 2;
                        u32 bH0 = w2s[bi], bH1 = w2s[bi + 1];
                        u32 bL0 = w2s[4096 + bi], bL1 = w2s[4096 + bi + 1];
                        mma16816(acc[nt], aH.x, aH.y, aH.z, aH.w, bH0, bH1);
                        mma16816(acc[nt], aH.x, aH.y, aH.z, aH.w, bL0, bL1);
                        mma16816(acc[nt], aL.x, aL.y, aL.z, aL.w, bH0, bH1);
                    }
                }
#pragma unroll
                for (int nt = 0; nt < 2; ++nt) {
                    int c = nt * 8 + c0;
                    myD[r0 * 17 + c]            = acc[nt][0];
                    myD[r0 * 17 + c + 1]        = acc[nt][1];
                    myD[(r0 + 8) * 17 + c]      = acc[nt][2];
                    myD[(r0 + 8) * 17 + c + 1]  = acc[nt][3];
                }
                __syncthreads();
#pragma unroll
                for (int pi = 0; pi < 3; ++pi) {
                    int p = tid + pi * 256;
                    if (p < 576) {
                        int rw = p / 9, o = p - rw * 9;
                        float v = yD[rw * 17 + o] + yD[1088 + rw * 17 + o] + __ldg(&b2[o]);
                        out[(rbY + rw) * 2934 + (t - 2) * 9 + o] = v;
                    }
                }
            }
            gbar(t);
        }
    }
}

// ---------------- launch -------------------------------------------------------
extern "C" void kernel_launch(void* const* d_in, const int* in_sizes, int n_in,
                              void* d_out, int out_size) {
    const float* x   = (const float*)d_in[0];
    const float* hx0 = (const float*)d_in[1];
    const float* cx0 = (const float*)d_in[2];
    const float* Wih = (const float*)d_in[3];
    const float* Whh = (const float*)d_in[4];
    const float* bih = (const float*)d_in[5];
    const float* bhh = (const float*)d_in[6];
    const float* W1  = (const float*)d_in[7];
    const float* b1  = (const float*)d_in[8];
    const float* W2  = (const float*)d_in[9];
    const float* b2  = (const float*)d_in[10];
    float* out = (float*)d_out;

    cudaFuncSetAttribute(main_kernel, cudaFuncAttributeMaxDynamicSharedMemorySize, SMEM_BYTES);

    prepB<<<10, 256>>>(bih, bhh, b1);
    prepW2frag<<<32, 256>>>(W2);
    prepWfrag<<<5120, 256>>>(Wih, Whh, W1);
    step0_kernel<<<128, 256>>>(x, hx0, cx0, Wih, Whh);
    main_kernel<<<NCTA, 256, SMEM_BYTES>>>(out, b2);
}